// round 7
// baseline (speedup 1.0000x reference)
#include <cuda_runtime.h>
#include <cstdint>

#define TBLOCK  256
#define NFILT   11
#define NCOLS   262144
#define NROWS   128
#define TILE    1024
#define TPB     8                    // tiles per block
#define STAGES  4
#define SF4     520                  // float4 per staged tile (1040 complexes)
#define NF4ROW  (NCOLS / 2)

typedef unsigned long long u64;

__device__ __forceinline__ u64 pack2(float lo, float hi) {
    u64 r; asm("mov.b64 %0, {%1, %2};" : "=l"(r) : "f"(lo), "f"(hi)); return r;
}
__device__ __forceinline__ void unpack2(u64 v, float& lo, float& hi) {
    asm("mov.b64 {%0, %1}, %2;" : "=f"(lo), "=f"(hi) : "l"(v));
}
__device__ __forceinline__ u64 fma2(u64 a, u64 b, u64 c) {
    u64 d; asm("fma.rn.f32x2 %0, %1, %2, %3;" : "=l"(d) : "l"(a), "l"(b), "l"(c)); return d;
}
__device__ __forceinline__ void cpa16(uint32_t s, const float4* g) {
    asm volatile("cp.async.cg.shared.global [%0], [%1], 16;" :: "r"(s), "l"(g));
}
__device__ __forceinline__ void cpa_commit() {
    asm volatile("cp.async.commit_group;");
}
template <int N> __device__ __forceinline__ void cpa_wait() {
    asm volatile("cp.async.wait_group %0;" :: "n"(N));
}

__global__ void __launch_bounds__(TBLOCK, 5) fir_cpasync_kernel(
    const float2* __restrict__ X, const float* __restrict__ phi,
    float2* __restrict__ Y)
{
    // AoS staging: sbuf[stage][f] covers complexes [tile0-6 + 2f, +1]
    __shared__ __align__(16) float4 sbuf[STAGES][SF4];

    const int tid   = threadIdx.x;
    const int row   = blockIdx.y;
    const int tbase = blockIdx.x * TPB;
    const float4* x4 = (const float4*)(X + (size_t)row * NCOLS);
    float2* yrow     = Y + (size_t)row * NCOLS;

    // Issue one tile's staging: float4 idx = tid, tid+256, (tid<8) tid+512.
    // Global float4 index f0(t) = t*512 - 3 (window origin tile0 - 6 complexes).
    #define ISSUE_TILE(t) do {                                                    \
        const int f0 = (tbase + (t)) * 512 - 3;                                   \
        const int buf = (t) & (STAGES - 1);                                       \
        {   int u = f0 + tid;                                                     \
            uint32_t d = (uint32_t)__cvta_generic_to_shared(&sbuf[buf][tid]);     \
            if (u >= 0 && u < NF4ROW) cpa16(d, x4 + u);                           \
            else sbuf[buf][tid] = make_float4(0.f, 0.f, 0.f, 0.f);                \
        }                                                                         \
        {   int u = f0 + 256 + tid;                                               \
            uint32_t d = (uint32_t)__cvta_generic_to_shared(&sbuf[buf][tid+256]); \
            if (u >= 0 && u < NF4ROW) cpa16(d, x4 + u);                           \
            else sbuf[buf][tid + 256] = make_float4(0.f, 0.f, 0.f, 0.f);          \
        }                                                                         \
        if (tid < 8) {                                                            \
            int u = f0 + 512 + tid;                                               \
            uint32_t d = (uint32_t)__cvta_generic_to_shared(&sbuf[buf][tid+512]); \
            if (u >= 0 && u < NF4ROW) cpa16(d, x4 + u);                           \
            else sbuf[buf][tid + 512] = make_float4(0.f, 0.f, 0.f, 0.f);          \
        }                                                                         \
        cpa_commit();                                                             \
    } while (0)

    // Prologue: 3 tiles in flight.
    ISSUE_TILE(0);
    ISSUE_TILE(1);
    ISSUE_TILE(2);

    // Coefficients A[k] = (wr_k, wi_k) — phi's native layout.
    u64 A[NFILT];
#pragma unroll
    for (int k = 0; k < NFILT; k++) {
        float2 w = __ldg(((const float2*)phi) + k);
        A[k] = pack2(w.x, w.y);
    }

#pragma unroll
    for (int it = 0; it < TPB; ++it) {
        // Tile `it` must be complete. Issued so far: tiles 0..min(it+2, TPB-1).
        if (it + 2 < TPB) cpa_wait<2>();
        else              cpa_wait<0>();
        __syncthreads();   // visibility of all threads' staged data; also
                           // guarantees compute(it-1) finished before buffer reuse.

        if (it + 3 < TPB) ISSUE_TILE(it + 3);   // writes buf (it+3)%4 = (it-1)%4

        // ---- Compute tile `it` ----
        // Thread window: complexes rel [4t, 4t+15] = float4 rel [2t, 2t+7].
        // Output i tap k -> rel complex j = i + k + 1, j in [1,14].
        const float4* w4 = &sbuf[it & (STAGES - 1)][2 * tid];
        float re[16], im[16];
#pragma unroll
        for (int q = 0; q < 8; q++) {
            float4 v = w4[q];
            re[2*q]   = v.x; im[2*q]   = v.y;
            re[2*q+1] = v.z; im[2*q+1] = v.w;
        }

        u64 P[4], Q[4];
#pragma unroll
        for (int i = 0; i < 4; i++) { P[i] = 0ull; Q[i] = 0ull; }

#pragma unroll
        for (int j = 1; j <= 14; j++) {
            u64 xrr = pack2(re[j], re[j]);
            u64 xii = pack2(im[j], im[j]);
#pragma unroll
            for (int i = 0; i < 4; i++) {
                const int k = j - 1 - i;            // compile-time after unroll
                if (k >= 0 && k < NFILT) {
                    P[i] = fma2(xrr, A[k], P[i]);
                    Q[i] = fma2(xii, A[k], Q[i]);
                }
            }
        }

        // out = (P.lo - Q.hi, P.hi + Q.lo)
        const int c0 = (tbase + it) * TILE + 4 * tid;
        float4 o0, o1;
        float prr, pri, qir, qii;
        unpack2(P[0], prr, pri); unpack2(Q[0], qir, qii); o0.x = prr - qii; o0.y = pri + qir;
        unpack2(P[1], prr, pri); unpack2(Q[1], qir, qii); o0.z = prr - qii; o0.w = pri + qir;
        unpack2(P[2], prr, pri); unpack2(Q[2], qir, qii); o1.x = prr - qii; o1.y = pri + qir;
        unpack2(P[3], prr, pri); unpack2(Q[3], qir, qii); o1.z = prr - qii; o1.w = pri + qir;

        float4* yo = (float4*)(yrow + c0);
        yo[0] = o0;
        yo[1] = o1;
    }
    #undef ISSUE_TILE
}

extern "C" void kernel_launch(void* const* d_in, const int* in_sizes, int n_in,
                              void* d_out, int out_size)
{
    const float2* X   = (const float2*)d_in[0];
    const float*  phi = (const float*)d_in[1];
    float2*       Y   = (float2*)d_out;

    dim3 grid(NCOLS / (TILE * TPB), NROWS);   // (32, 128)
    fir_cpasync_kernel<<<grid, TBLOCK>>>(X, phi, Y);
}

// round 8
// speedup vs baseline: 1.2433x; 1.2433x over previous
#include <cuda_runtime.h>

#define TBLOCK  128
#define NFILT   11
#define NCOLS   262144
#define NROWS   128
#define TILE    512                // outputs per tile (TBLOCK * 4)
#define TPB     8                  // tiles per block (pipelined)
#define SW      528                // staged complexes: cols [T0-6, T0+522)
#define NF4ROW  (NCOLS / 2)        // float4s per row

typedef unsigned long long u64;

__device__ __forceinline__ u64 pack2(float lo, float hi) {
    u64 r; asm("mov.b64 %0, {%1, %2};" : "=l"(r) : "f"(lo), "f"(hi)); return r;
}
__device__ __forceinline__ void unpack2(u64 v, float& lo, float& hi) {
    asm("mov.b64 {%0, %1}, %2;" : "=f"(lo), "=f"(hi) : "l"(v));
}
__device__ __forceinline__ u64 fma2(u64 a, u64 b, u64 c) {
    u64 d; asm("fma.rn.f32x2 %0, %1, %2, %3;" : "=l"(d) : "l"(a), "l"(b), "l"(c)); return d;
}
__device__ __forceinline__ float4 ldz(const float4* x4, int u) {
    // SAME padding: zeros outside the row
    if (u >= 0 && u < NF4ROW) return __ldg(x4 + u);
    return make_float4(0.f, 0.f, 0.f, 0.f);
}

__global__ void __launch_bounds__(TBLOCK) fir_pipe3_kernel(
    const float2* __restrict__ X, const float* __restrict__ phi,
    float2* __restrict__ Y)
{
    __shared__ float s_re[2][SW];
    __shared__ float s_im[2][SW];

    const int tid = threadIdx.x;
    const int row = blockIdx.y;
    const float4* x4 = (const float4*)(X + (size_t)row * NCOLS);
    float2* yrow     = Y + (size_t)row * NCOLS;

    // Coefficients A[k] = (wr_k, wi_k) — phi's native layout.
    u64 A[NFILT];
#pragma unroll
    for (int k = 0; k < NFILT; k++) {
        float2 w = __ldg(((const float2*)phi) + k);
        A[k] = pack2(w.x, w.y);
    }

    const int tbase = blockIdx.x * TPB;

    // Register stage holds ONE tile (the next to be STS'd).
    float4 r0, r1, r2;

    // Tile t covers cols [T0, T0+512), T0 = (tbase+t)*512.
    // smem j <-> col T0 - 6 + j. First float4 index f0 = (tbase+t)*256 - 3.
    #define LOAD_TILE(t)  do {                                   \
        const int f0 = (tbase + (t)) * 256 - 3;                  \
        r0 = ldz(x4, f0 + tid);                                  \
        r1 = ldz(x4, f0 + 128 + tid);                            \
        r2 = (tid < 8) ? ldz(x4, f0 + 256 + tid)                 \
                       : make_float4(0.f, 0.f, 0.f, 0.f);        \
    } while (0)

    #define STORE_TILE(buf) do {                                                  \
        *(float2*)(&s_re[buf][2 * tid])         = make_float2(r0.x, r0.z);        \
        *(float2*)(&s_im[buf][2 * tid])         = make_float2(r0.y, r0.w);        \
        *(float2*)(&s_re[buf][2 * (tid + 128)]) = make_float2(r1.x, r1.z);        \
        *(float2*)(&s_im[buf][2 * (tid + 128)]) = make_float2(r1.y, r1.w);        \
        if (tid < 8) {                                                            \
            *(float2*)(&s_re[buf][2 * (tid + 256)]) = make_float2(r2.x, r2.z);    \
            *(float2*)(&s_im[buf][2 * (tid + 256)]) = make_float2(r2.y, r2.w);    \
        }                                                                          \
    } while (0)

    // ---- Prologue: tile 0 staged, tile 1 loaded into registers ----
    LOAD_TILE(0);
    STORE_TILE(0);
    LOAD_TILE(1);
    __syncthreads();

#pragma unroll
    for (int it = 0; it < TPB; ++it) {
        const int b = it & 1;

        // Stage tile it+1 (regs -> other buffer), then start LDG of it+2.
        if (it + 1 < TPB) {
            STORE_TILE(b ^ 1);
            if (it + 2 < TPB) LOAD_TILE(it + 2);
        }

        // ---- Compute tile it from buffer b ----
        // Window floats [4t, 4t+15]; taps use j = i + k + 1 in [4t+1, 4t+14].
        float re[16], im[16];
        {
            const float4* pr = (const float4*)(&s_re[b][4 * tid]);
            const float4* pi = (const float4*)(&s_im[b][4 * tid]);
#pragma unroll
            for (int q = 0; q < 4; q++) {
                float4 vr = pr[q], vi = pi[q];
                re[4*q] = vr.x; re[4*q+1] = vr.y; re[4*q+2] = vr.z; re[4*q+3] = vr.w;
                im[4*q] = vi.x; im[4*q+1] = vi.y; im[4*q+2] = vi.z; im[4*q+3] = vi.w;
            }
        }

        u64 P[4], Q[4];
#pragma unroll
        for (int i = 0; i < 4; i++) { P[i] = 0ull; Q[i] = 0ull; }

#pragma unroll
        for (int j = 1; j <= 14; j++) {
            u64 xrr = pack2(re[j], re[j]);
            u64 xii = pack2(im[j], im[j]);
#pragma unroll
            for (int i = 0; i < 4; i++) {
                const int k = j - 1 - i;            // compile-time after unroll
                if (k >= 0 && k < NFILT) {
                    P[i] = fma2(xrr, A[k], P[i]);
                    Q[i] = fma2(xii, A[k], Q[i]);
                }
            }
        }

        // out = (P.lo - Q.hi, P.hi + Q.lo)
        const int c0 = (tbase + it) * TILE + 4 * tid;
        float4 o0, o1;
        float prr, pri, qir, qii;
        unpack2(P[0], prr, pri); unpack2(Q[0], qir, qii); o0.x = prr - qii; o0.y = pri + qir;
        unpack2(P[1], prr, pri); unpack2(Q[1], qir, qii); o0.z = prr - qii; o0.w = pri + qir;
        unpack2(P[2], prr, pri); unpack2(Q[2], qir, qii); o1.x = prr - qii; o1.y = pri + qir;
        unpack2(P[3], prr, pri); unpack2(Q[3], qir, qii); o1.z = prr - qii; o1.w = pri + qir;

        float4* yo = (float4*)(yrow + c0);
        yo[0] = o0;
        yo[1] = o1;

        __syncthreads();
    }
    #undef LOAD_TILE
    #undef STORE_TILE
}

extern "C" void kernel_launch(void* const* d_in, const int* in_sizes, int n_in,
                              void* d_out, int out_size)
{
    const float2* X   = (const float2*)d_in[0];
    const float*  phi = (const float*)d_in[1];
    float2*       Y   = (float2*)d_out;

    dim3 grid(NCOLS / (TILE * TPB), NROWS);   // (64, 128)
    fir_pipe3_kernel<<<grid, TBLOCK>>>(X, phi, Y);
}

// round 9
// speedup vs baseline: 1.2503x; 1.0056x over previous
#include <cuda_runtime.h>

#define TBLOCK  128
#define NFILT   11
#define NCOLS   262144
#define NROWS   128
#define TILE    512                // outputs per tile (TBLOCK * 4)
#define TPB     4                  // tiles per block (pipelined)
#define SW      528                // staged complexes: cols [T0-6, T0+522)
#define NF4ROW  (NCOLS / 2)        // float4s per row

typedef unsigned long long u64;

__device__ __forceinline__ u64 pack2(float lo, float hi) {
    u64 r; asm("mov.b64 %0, {%1, %2};" : "=l"(r) : "f"(lo), "f"(hi)); return r;
}
__device__ __forceinline__ void unpack2(u64 v, float& lo, float& hi) {
    asm("mov.b64 {%0, %1}, %2;" : "=f"(lo), "=f"(hi) : "l"(v));
}
__device__ __forceinline__ u64 fma2(u64 a, u64 b, u64 c) {
    u64 d; asm("fma.rn.f32x2 %0, %1, %2, %3;" : "=l"(d) : "l"(a), "l"(b), "l"(c)); return d;
}
__device__ __forceinline__ float4 ldz(const float4* x4, int u) {
    // SAME padding: zeros outside the row
    if (u >= 0 && u < NF4ROW) return __ldg(x4 + u);
    return make_float4(0.f, 0.f, 0.f, 0.f);
}

__global__ void __launch_bounds__(TBLOCK, 10) fir_pipe4_kernel(
    const float2* __restrict__ X, const float* __restrict__ phi,
    float2* __restrict__ Y)
{
    __shared__ float s_re[2][SW];
    __shared__ float s_im[2][SW];

    const int tid = threadIdx.x;
    const int row = blockIdx.y;
    const float4* x4 = (const float4*)(X + (size_t)row * NCOLS);
    float2* yrow     = Y + (size_t)row * NCOLS;

    // Coefficients A[k] = (wr_k, wi_k) — phi's native layout.
    u64 A[NFILT];
#pragma unroll
    for (int k = 0; k < NFILT; k++) {
        float2 w = __ldg(((const float2*)phi) + k);
        A[k] = pack2(w.x, w.y);
    }

    const int tbase = blockIdx.x * TPB;

    // Register stage holds ONE tile (the next to be STS'd).
    float4 r0, r1, r2;

    // Tile t covers cols [T0, T0+512), T0 = (tbase+t)*512.
    // smem j <-> col T0 - 6 + j. First float4 index f0 = (tbase+t)*256 - 3.
    #define LOAD_TILE(t)  do {                                   \
        const int f0 = (tbase + (t)) * 256 - 3;                  \
        r0 = ldz(x4, f0 + tid);                                  \
        r1 = ldz(x4, f0 + 128 + tid);                            \
        r2 = (tid < 8) ? ldz(x4, f0 + 256 + tid)                 \
                       : make_float4(0.f, 0.f, 0.f, 0.f);        \
    } while (0)

    #define STORE_TILE(buf) do {                                                  \
        *(float2*)(&s_re[buf][2 * tid])         = make_float2(r0.x, r0.z);        \
        *(float2*)(&s_im[buf][2 * tid])         = make_float2(r0.y, r0.w);        \
        *(float2*)(&s_re[buf][2 * (tid + 128)]) = make_float2(r1.x, r1.z);        \
        *(float2*)(&s_im[buf][2 * (tid + 128)]) = make_float2(r1.y, r1.w);        \
        if (tid < 8) {                                                            \
            *(float2*)(&s_re[buf][2 * (tid + 256)]) = make_float2(r2.x, r2.z);    \
            *(float2*)(&s_im[buf][2 * (tid + 256)]) = make_float2(r2.y, r2.w);    \
        }                                                                          \
    } while (0)

    // ---- Prologue: tile 0 staged, tile 1 loaded into registers ----
    LOAD_TILE(0);
    STORE_TILE(0);
    LOAD_TILE(1);
    __syncthreads();

#pragma unroll
    for (int it = 0; it < TPB; ++it) {
        const int b = it & 1;

        // Stage tile it+1 (regs -> other buffer), then start LDG of it+2.
        if (it + 1 < TPB) {
            STORE_TILE(b ^ 1);
            if (it + 2 < TPB) LOAD_TILE(it + 2);
        }

        // ---- Compute tile it from buffer b ----
        // Window floats [4t, 4t+15]; taps use j = i + k + 1 in [4t+1, 4t+14].
        float re[16], im[16];
        {
            const float4* pr = (const float4*)(&s_re[b][4 * tid]);
            const float4* pi = (const float4*)(&s_im[b][4 * tid]);
#pragma unroll
            for (int q = 0; q < 4; q++) {
                float4 vr = pr[q], vi = pi[q];
                re[4*q] = vr.x; re[4*q+1] = vr.y; re[4*q+2] = vr.z; re[4*q+3] = vr.w;
                im[4*q] = vi.x; im[4*q+1] = vi.y; im[4*q+2] = vi.z; im[4*q+3] = vi.w;
            }
        }

        u64 P[4], Q[4];
#pragma unroll
        for (int i = 0; i < 4; i++) { P[i] = 0ull; Q[i] = 0ull; }

#pragma unroll
        for (int j = 1; j <= 14; j++) {
            u64 xrr = pack2(re[j], re[j]);
            u64 xii = pack2(im[j], im[j]);
#pragma unroll
            for (int i = 0; i < 4; i++) {
                const int k = j - 1 - i;            // compile-time after unroll
                if (k >= 0 && k < NFILT) {
                    P[i] = fma2(xrr, A[k], P[i]);
                    Q[i] = fma2(xii, A[k], Q[i]);
                }
            }
        }

        // out = (P.lo - Q.hi, P.hi + Q.lo)
        const int c0 = (tbase + it) * TILE + 4 * tid;
        float4 o0, o1;
        float prr, pri, qir, qii;
        unpack2(P[0], prr, pri); unpack2(Q[0], qir, qii); o0.x = prr - qii; o0.y = pri + qir;
        unpack2(P[1], prr, pri); unpack2(Q[1], qir, qii); o0.z = prr - qii; o0.w = pri + qir;
        unpack2(P[2], prr, pri); unpack2(Q[2], qir, qii); o1.x = prr - qii; o1.y = pri + qir;
        unpack2(P[3], prr, pri); unpack2(Q[3], qir, qii); o1.z = prr - qii; o1.w = pri + qir;

        float4* yo = (float4*)(yrow + c0);
        yo[0] = o0;
        yo[1] = o1;

        __syncthreads();
    }
    #undef LOAD_TILE
    #undef STORE_TILE
}

extern "C" void kernel_launch(void* const* d_in, const int* in_sizes, int n_in,
                              void* d_out, int out_size)
{
    const float2* X   = (const float2*)d_in[0];
    const float*  phi = (const float*)d_in[1];
    float2*       Y   = (float2*)d_out;

    dim3 grid(NCOLS / (TILE * TPB), NROWS);   // (128, 128)
    fir_pipe4_kernel<<<grid, TBLOCK>>>(X, phi, Y);
}

// round 10
// speedup vs baseline: 1.2696x; 1.0155x over previous
#include <cuda_runtime.h>

#define TBLOCK  128
#define NWARP   4
#define NFILT   11
#define NCOLS   262144
#define NROWS   128
#define WTILE   128                 // outputs per warp-tile
#define TPW     4                   // tiles per warp (pipelined chain)
#define SWF     144                 // floats per array per warp slice (need 140)
#define NF4ROW  (NCOLS / 2)

typedef unsigned long long u64;

__device__ __forceinline__ u64 pack2(float lo, float hi) {
    u64 r; asm("mov.b64 %0, {%1, %2};" : "=l"(r) : "f"(lo), "f"(hi)); return r;
}
__device__ __forceinline__ void unpack2(u64 v, float& lo, float& hi) {
    asm("mov.b64 {%0, %1}, %2;" : "=f"(lo), "=f"(hi) : "l"(v));
}
__device__ __forceinline__ u64 fma2(u64 a, u64 b, u64 c) {
    u64 d; asm("fma.rn.f32x2 %0, %1, %2, %3;" : "=l"(d) : "l"(a), "l"(b), "l"(c)); return d;
}
__device__ __forceinline__ float4 ldz(const float4* x4, int u) {
    if (u >= 0 && u < NF4ROW) return __ldg(x4 + u);
    return make_float4(0.f, 0.f, 0.f, 0.f);
}

__global__ void __launch_bounds__(TBLOCK, 10) fir_warp_kernel(
    const float2* __restrict__ X, const float* __restrict__ phi,
    float2* __restrict__ Y)
{
    // Per-warp private double-buffered SoA slices.
    __shared__ float s_re[NWARP][2][SWF];
    __shared__ float s_im[NWARP][2][SWF];

    const int lane = threadIdx.x & 31;
    const int wid  = threadIdx.x >> 5;
    const int row  = blockIdx.y;
    const float4* x4 = (const float4*)(X + (size_t)row * NCOLS);
    float2* yrow     = Y + (size_t)row * NCOLS;

    // Coefficients A[k] = (wr_k, wi_k)
    u64 A[NFILT];
#pragma unroll
    for (int k = 0; k < NFILT; k++) {
        float2 w = __ldg(((const float2*)phi) + k);
        A[k] = pack2(w.x, w.y);
    }

    // This warp's chain: tiles [wt0, wt0 + TPW), tile t covers cols [t*128, t*128+128)
    const int wt0 = (blockIdx.x * NWARP + wid) * TPW;

    float* const re0 = &s_re[wid][0][0];
    float* const im0 = &s_im[wid][0][0];
    float* const re1 = &s_re[wid][1][0];
    float* const im1 = &s_im[wid][1][0];

    // Register stage: one tile (72 gmem float4 spread over the warp).
    float4 r0, r1, r2;

    // Tile t: window complexes [T0-6, T0+138), T0 = (wt0+t)*128.
    // gmem float4 start g0 = T0/2 - 3. Lane loads g0+l, g0+32+l, (l<8) g0+64+l.
    #define LOAD_TILE(t) do {                                    \
        const int g0 = (wt0 + (t)) * 64 - 3;                     \
        r0 = ldz(x4, g0 + lane);                                 \
        r1 = ldz(x4, g0 + 32 + lane);                            \
        r2 = (lane < 8) ? ldz(x4, g0 + 64 + lane)                \
                        : make_float4(0.f, 0.f, 0.f, 0.f);       \
    } while (0)

    // gmem float4 #m (rel) = complexes {2m, 2m+1} -> re/im float2 at 2m.
    #define STORE_TILE(pre, pim) do {                                     \
        *(float2*)((pre) + 2 * lane)          = make_float2(r0.x, r0.z);  \
        *(float2*)((pim) + 2 * lane)          = make_float2(r0.y, r0.w);  \
        *(float2*)((pre) + 64 + 2 * lane)     = make_float2(r1.x, r1.z);  \
        *(float2*)((pim) + 64 + 2 * lane)     = make_float2(r1.y, r1.w);  \
        if (lane < 8) {                                                   \
            *(float2*)((pre) + 128 + 2 * lane) = make_float2(r2.x, r2.z); \
            *(float2*)((pim) + 128 + 2 * lane) = make_float2(r2.y, r2.w); \
        }                                                                 \
    } while (0)

    // ---- Prologue: tile 0 staged, tile 1 in registers ----
    LOAD_TILE(0);
    STORE_TILE(re0, im0);
    LOAD_TILE(1);
    __syncwarp();

#pragma unroll
    for (int it = 0; it < TPW; ++it) {
        float* const bre = (it & 1) ? re1 : re0;
        float* const bim = (it & 1) ? im1 : im0;

        if (it + 1 < TPW) {
            float* const nre = (it & 1) ? re0 : re1;
            float* const nim = (it & 1) ? im0 : im1;
            STORE_TILE(nre, nim);
            if (it + 2 < TPW) LOAD_TILE(it + 2);
        }

        // ---- Compute tile `it`: window floats [4l, 4l+15] of this warp's slice.
        // Output i (col T0 + 4l + i), tap k -> j = 4l + i + k + 1.
        float re[16], im[16];
        {
            const float4* pr = (const float4*)(bre + 4 * lane);
            const float4* pi = (const float4*)(bim + 4 * lane);
#pragma unroll
            for (int q = 0; q < 4; q++) {
                float4 vr = pr[q], vi = pi[q];
                re[4*q] = vr.x; re[4*q+1] = vr.y; re[4*q+2] = vr.z; re[4*q+3] = vr.w;
                im[4*q] = vi.x; im[4*q+1] = vi.y; im[4*q+2] = vi.z; im[4*q+3] = vi.w;
            }
        }

        u64 P[4], Q[4];
#pragma unroll
        for (int i = 0; i < 4; i++) { P[i] = 0ull; Q[i] = 0ull; }

#pragma unroll
        for (int j = 1; j <= 14; j++) {
            u64 xrr = pack2(re[j], re[j]);
            u64 xii = pack2(im[j], im[j]);
#pragma unroll
            for (int i = 0; i < 4; i++) {
                const int k = j - 1 - i;            // compile-time after unroll
                if (k >= 0 && k < NFILT) {
                    P[i] = fma2(xrr, A[k], P[i]);
                    Q[i] = fma2(xii, A[k], Q[i]);
                }
            }
        }

        // out = (P.lo - Q.hi, P.hi + Q.lo)
        const int c0 = (wt0 + it) * WTILE + 4 * lane;
        float4 o0, o1;
        float prr, pri, qir, qii;
        unpack2(P[0], prr, pri); unpack2(Q[0], qir, qii); o0.x = prr - qii; o0.y = pri + qir;
        unpack2(P[1], prr, pri); unpack2(Q[1], qir, qii); o0.z = prr - qii; o0.w = pri + qir;
        unpack2(P[2], prr, pri); unpack2(Q[2], qir, qii); o1.x = prr - qii; o1.y = pri + qir;
        unpack2(P[3], prr, pri); unpack2(Q[3], qir, qii); o1.z = prr - qii; o1.w = pri + qir;

        float4* yo = (float4*)(yrow + c0);
        yo[0] = o0;
        yo[1] = o1;

        __syncwarp();   // orders this iter's STS before next iter's LDS
    }
    #undef LOAD_TILE
    #undef STORE_TILE
}

extern "C" void kernel_launch(void* const* d_in, const int* in_sizes, int n_in,
                              void* d_out, int out_size)
{
    const float2* X   = (const float2*)d_in[0];
    const float*  phi = (const float*)d_in[1];
    float2*       Y   = (float2*)d_out;

    // warp-tiles per row = 2048; per block = NWARP*TPW = 16 -> 128 blocks/row
    dim3 grid(NCOLS / (WTILE * NWARP * TPW), NROWS);   // (128, 128)
    fir_warp_kernel<<<grid, TBLOCK>>>(X, phi, Y);
}